// round 11
// baseline (speedup 1.0000x reference)
#include <cuda_runtime.h>
#include <cuda_bf16.h>
#include <cstdint>

#define B_   32
#define C_   128
#define CO_  96
#define H_   64
#define W_   64
#define HW_  4096
#define HP_  66
#define WP_  66
#define KTOT 1152   // 9 taps * 128 ci

// ---------------- device scratch (no allocations allowed) ----------------
__device__ __align__(16) __nv_bfloat16 g_xh[(size_t)B_ * HP_ * WP_ * C_]; // padded NHWC hi
__device__ __align__(16) __nv_bfloat16 g_xl[(size_t)B_ * HP_ * WP_ * C_]; // padded NHWC lo
__device__ __align__(16) __nv_bfloat16 g_wh[CO_ * KTOT];  // A hi: [co][tap*128+ci]
__device__ __align__(16) __nv_bfloat16 g_wl[CO_ * KTOT];  // A lo
__device__ int    g_idx[3 * C_];
__device__ float  g_med[(size_t)B_ * C_ * HW_];
__device__ float2 g_part[C_ * 8];
__device__ float2 g_sb[C_];

// ---------------- PTX helpers (all sm_80-era: safe for compute_103) ----------------
__device__ __forceinline__ uint32_t smem_u32(const void* p) {
    uint32_t a;
    asm("{ .reg .u64 t; cvta.to.shared.u64 t, %1; cvt.u32.u64 %0, t; }" : "=r"(a) : "l"(p));
    return a;
}
__device__ __forceinline__ void ldsm4(uint32_t* r, uint32_t addr) {
    asm volatile("ldmatrix.sync.aligned.m8n8.x4.shared.b16 {%0,%1,%2,%3}, [%4];"
        : "=r"(r[0]), "=r"(r[1]), "=r"(r[2]), "=r"(r[3]) : "r"(addr));
}
__device__ __forceinline__ void mma16816(float* d, const uint32_t* a, const uint32_t* b) {
    asm volatile("mma.sync.aligned.m16n8k16.row.col.f32.bf16.bf16.f32 "
        "{%0,%1,%2,%3}, {%4,%5,%6,%7}, {%8,%9}, {%0,%1,%2,%3};"
        : "+f"(d[0]), "+f"(d[1]), "+f"(d[2]), "+f"(d[3])
        : "r"(a[0]), "r"(a[1]), "r"(a[2]), "r"(a[3]), "r"(b[0]), "r"(b[1]));
}
#define CP_ASYNC16(dst, src) \
    asm volatile("cp.async.cg.shared.global [%0], [%1], 16;" :: "r"(dst), "l"(src) : "memory")
#define CP_COMMIT() asm volatile("cp.async.commit_group;" ::: "memory")
#define CP_WAIT1()  asm volatile("cp.async.wait_group 1;" ::: "memory")
#define CP_WAIT0()  asm volatile("cp.async.wait_group 0;" ::: "memory")

// stage layout (bytes, within one 64512-B stage):
//   Ah @ 0      : 96  rows x 144B pitch (64 ci used)
//   Al @ 13824
//   Bh @ 27648  : 128 rows x 144B pitch
//   Bl @ 46080
#define ST_AL 13824u
#define ST_BH 27648u
#define ST_BL 46080u
#define ST_SZ 64512u

// ---------------- 1) one-hot indices from hs ----------------
__global__ void idx_kernel(const float* __restrict__ hs) {
    int t = blockIdx.x * blockDim.x + threadIdx.x;
    if (t >= 3 * C_) return;
    int j = t >> 7, c = t & 127;
    int d = 0;
    for (int dd = 0; dd < 32; ++dd)
        if (hs[(j * 32 + dd) * C_ + c] > 0.5f) d = dd;
    g_idx[t] = d;
}

// ---------------- 2) sketched weights -> hi/lo, [co][tap*128+ci] ----------------
__global__ void wsk_kernel(const float* __restrict__ w2, const float* __restrict__ ss) {
    int e = blockIdx.x * 256 + threadIdx.x;
    if (e >= CO_ * KTOT) return;
    int ci = e & 127, tap = (e >> 7) % 9, co = e / KTOT;
    int j = co >> 5, d = co & 31;
    float sum = 0.f;
    for (int c = 0; c < C_; ++c) {
        int   ic = g_idx[j * C_ + c];
        float wv = w2[(c * C_ + ci) * 9 + tap];
        sum += (ic == d) ? ss[j * C_ + c] * wv : 0.f;
    }
    __nv_bfloat16 hi = __float2bfloat16(sum);
    g_wh[e] = hi;
    g_wl[e] = __float2bfloat16(sum - __bfloat162float(hi));
}

// ---------------- 3a) zero padded borders of g_xh / g_xl ----------------
__global__ void zero_kernel() {
    int t = blockIdx.x * 256 + threadIdx.x;          // B_ * 260 * 16
    if (t >= B_ * 260 * 16) return;
    int v  = t & 15;
    int pb = (t >> 4) % 260;
    int b  = t / (260 * 16);
    int h, w;
    if (pb < 66)       { h = 0;  w = pb; }
    else if (pb < 132) { h = 65; w = pb - 66; }
    else { int q = pb - 132; h = 1 + (q >> 1); w = (q & 1) * 65; }
    size_t off = (((size_t)b * HP_ + h) * WP_ + w) * C_ + v * 8;
    *(uint4*)(g_xh + off) = make_uint4(0, 0, 0, 0);
    *(uint4*)(g_xl + off) = make_uint4(0, 0, 0, 0);
}

// ---------------- 3b) NCHW fp32 -> padded NHWC bf16 hi/lo ----------------
__global__ __launch_bounds__(256) void xT_kernel(const float* __restrict__ x) {
    __shared__ float sm[128 * 65];
    const int t = threadIdx.x, h = blockIdx.x, b = blockIdx.y;
    const float* xp = x + (size_t)b * C_ * HW_ + h * W_;
#pragma unroll
    for (int k = 0; k < 32; ++k) {
        int idx = (k << 8) + t;
        int c = idx >> 6, w = idx & 63;
        sm[c * 65 + w] = xp[(size_t)c * HW_ + w];
    }
    __syncthreads();
    size_t dbase = (((size_t)b * HP_ + h + 1) * WP_ + 1) * C_;
#pragma unroll
    for (int k = 0; k < 16; ++k) {
        int idx = (k << 8) + t;
        int w = idx >> 6, c2 = idx & 63;
        float f0 = sm[(2 * c2) * 65 + w];
        float f1 = sm[(2 * c2 + 1) * 65 + w];
        __nv_bfloat162 hh = __floats2bfloat162_rn(f0, f1);
        float r0 = f0 - __bfloat162float(hh.x);
        float r1 = f1 - __bfloat162float(hh.y);
        __nv_bfloat162 ll = __floats2bfloat162_rn(r0, r1);
        size_t o = dbase + (size_t)w * C_ + 2 * c2;
        *(unsigned*)(g_xh + o) = *(unsigned*)&hh;
        *(unsigned*)(g_xl + o) = *(unsigned*)&ll;
    }
}

// ---------------- 4) mma.sync conv, cp.async double-buffered ----------------
__device__ __forceinline__ void stage_chunk(
    int chunk, uint32_t sb,
    const __nv_bfloat16* __restrict__ xbh,
    const __nv_bfloat16* __restrict__ xbl, int tid)
{
    const int tap = chunk >> 1, half = chunk & 1;
    const int kh = tap / 3, kw = tap - kh * 3;
    const int koff = tap * 128 + half * 64;
    const __nv_bfloat16* wh = g_wh + koff;
    const __nv_bfloat16* wl = g_wl + koff;
    const size_t xoff = ((size_t)kh * WP_ + kw) * C_ + half * 64;
    const __nv_bfloat16* xh = xbh + xoff;
    const __nv_bfloat16* xl = xbl + xoff;
#pragma unroll
    for (int k = 0; k < 3; ++k) {
        int g = tid + (k << 8);
        int row = g >> 3, sub = g & 7;
        uint32_t d = (uint32_t)(row * 144 + sub * 16);
        const size_t so = (size_t)row * KTOT + sub * 8;
        CP_ASYNC16(sb + d,         wh + so);
        CP_ASYNC16(sb + ST_AL + d, wl + so);
    }
#pragma unroll
    for (int k = 0; k < 4; ++k) {
        int g = tid + (k << 8);
        int n = g >> 3, sub = g & 7;
        int r = n >> 6, wn = n & 63;
        size_t so = ((size_t)r * WP_ + wn) * C_ + sub * 8;
        uint32_t d = (uint32_t)(n * 144 + sub * 16);
        CP_ASYNC16(sb + ST_BH + d, xh + so);
        CP_ASYNC16(sb + ST_BL + d, xl + so);
    }
}

__global__ __launch_bounds__(256, 1)
void conv_mma_kernel(const float* __restrict__ ss) {
    extern __shared__ __nv_bfloat16 dsm[];
    const int tid = threadIdx.x, warp = tid >> 5, lane = tid & 31;
    const int b = blockIdx.y, h0 = blockIdx.x << 1;   // 2 output rows per CTA
    const int m0 = (warp >> 2) * 48;                  // 2 warps in M
    const int n0 = (warp & 3) * 32;                   // 4 warps in N

    const uint32_t sb0 = smem_u32(dsm);
    const uint32_t sb1 = sb0 + ST_SZ;
    const __nv_bfloat16* xbh = g_xh + (((size_t)b * HP_ + h0) * WP_) * C_;
    const __nv_bfloat16* xbl = g_xl + (((size_t)b * HP_ + h0) * WP_) * C_;

    // ldmatrix per-lane relative offsets (within a stage region)
    uint32_t a_rel[3];
#pragma unroll
    for (int ti = 0; ti < 3; ++ti)
        a_rel[ti] = (uint32_t)((m0 + ti * 16 + (lane & 15)) * 144 + (lane >> 4) * 16);
    uint32_t b_rel[2];
    {
        int o = lane >> 3;
#pragma unroll
        for (int u = 0; u < 2; ++u) {
            int pix = n0 + u * 16 + (o >> 1) * 8 + (lane & 7);
            b_rel[u] = (uint32_t)(pix * 144 + (o & 1) * 16);
        }
    }

    float acc[3][4][4];
#pragma unroll
    for (int ti = 0; ti < 3; ++ti)
#pragma unroll
        for (int tj = 0; tj < 4; ++tj)
#pragma unroll
            for (int v = 0; v < 4; ++v) acc[ti][tj][v] = 0.f;

    stage_chunk(0, sb0, xbh, xbl, tid);
    CP_COMMIT();

#pragma unroll 1
    for (int i = 0; i < 18; ++i) {
        const uint32_t cur = (i & 1) ? sb1 : sb0;
        if (i + 1 < 18) {
            stage_chunk(i + 1, (i & 1) ? sb0 : sb1, xbh, xbl, tid);
            CP_COMMIT();
            CP_WAIT1();
        } else {
            CP_WAIT0();
        }
        __syncthreads();

#pragma unroll
        for (int s = 0; s < 4; ++s) {
            uint32_t ah[3][4], al[3][4], bh[8], bl[8];
#pragma unroll
            for (int ti = 0; ti < 3; ++ti) {
                ldsm4(ah[ti], cur + a_rel[ti] + s * 32);
                ldsm4(al[ti], cur + ST_AL + a_rel[ti] + s * 32);
            }
#pragma unroll
            for (int u = 0; u < 2; ++u) {
                ldsm4(&bh[u * 4], cur + ST_BH + b_rel[u] + s * 32);
                ldsm4(&bl[u * 4], cur + ST_BL + b_rel[u] + s * 32);
            }
#pragma unroll
            for (int ti = 0; ti < 3; ++ti)
#pragma unroll
                for (int tj = 0; tj < 4; ++tj) {
                    mma16816(acc[ti][tj], ah[ti], &bh[tj * 2]);  // Wh * Xh
                    mma16816(acc[ti][tj], al[ti], &bh[tj * 2]);  // Wl * Xh
                    mma16816(acc[ti][tj], ah[ti], &bl[tj * 2]);  // Wh * Xl
                }
        }
        __syncthreads();   // all warps done reading `cur` before it is overwritten
    }

    // ---- accumulators -> SMEM yt[96][132] (reuse stage-0 smem) ----
    float* yt = (float*)dsm;
#pragma unroll
    for (int ti = 0; ti < 3; ++ti)
#pragma unroll
        for (int tj = 0; tj < 4; ++tj) {
            int row = m0 + ti * 16 + (lane >> 2);
            int col = n0 + tj * 8 + (lane & 3) * 2;
            *(float2*)&yt[row * 132 + col]       = make_float2(acc[ti][tj][0], acc[ti][tj][1]);
            *(float2*)&yt[(row + 8) * 132 + col] = make_float2(acc[ti][tj][2], acc[ti][tj][3]);
        }
    __syncthreads();

    // ---- unsketch (gather + sign) + median-of-3, coalesced g_med store ----
    const int sp = tid & 127, cg = tid >> 7;
    const int hh = h0 + (sp >> 6), wn = sp & 63;
    float* mbase = g_med + ((size_t)b * C_) * HW_ + hh * W_ + wn;
#pragma unroll 1
    for (int cc = 0; cc < 64; ++cc) {
        int c = (cg << 6) + cc;
        int i0 = g_idx[c], i1 = g_idx[C_ + c], i2 = g_idx[2 * C_ + c];
        float s0 = ss[c], s1 = ss[C_ + c], s2 = ss[2 * C_ + c];
        float v0 = s0 * yt[i0 * 132 + sp];
        float v1 = s1 * yt[(32 + i1) * 132 + sp];
        float v2 = s2 * yt[(64 + i2) * 132 + sp];
        float mx = fmaxf(v0, v1), mn = fminf(v0, v1);
        mbase[(size_t)c * HW_] = fmaxf(mn, fminf(mx, v2));
    }
}

// ---------------- 5) BN stats, two-stage ----------------
__global__ void stats1_kernel() {
    const int c = blockIdx.x, q = blockIdx.y, tid = threadIdx.x;
    float s = 0.f, qq = 0.f;
    for (int bb = q * 4; bb < q * 4 + 4; ++bb) {
        const float4* p = (const float4*)(g_med + ((size_t)bb * C_ + c) * HW_);
        for (int i = tid; i < HW_ / 4; i += 256) {
            float4 v = p[i];
            s += v.x + v.y + v.z + v.w;
            qq = fmaf(v.x, v.x, fmaf(v.y, v.y, fmaf(v.z, v.z, fmaf(v.w, v.w, qq))));
        }
    }
    __shared__ float rs[8], rq[8];
#pragma unroll
    for (int o = 16; o; o >>= 1) {
        s  += __shfl_down_sync(0xffffffffu, s,  o);
        qq += __shfl_down_sync(0xffffffffu, qq, o);
    }
    if ((tid & 31) == 0) { rs[tid >> 5] = s; rq[tid >> 5] = qq; }
    __syncthreads();
    if (tid == 0) {
        float S = 0.f, Q = 0.f;
        for (int i = 0; i < 8; ++i) { S += rs[i]; Q += rq[i]; }
        g_part[c * 8 + q] = make_float2(S, Q);
    }
}
__global__ void stats2_kernel(const float* __restrict__ gamma2,
                              const float* __restrict__ beta2) {
    int c = threadIdx.x;
    float S = 0.f, Q = 0.f;
    for (int q = 0; q < 8; ++q) { float2 p = g_part[c * 8 + q]; S += p.x; Q += p.y; }
    const float invn = 1.f / (float)(B_ * HW_);
    float mean  = S * invn;
    float var   = Q * invn - mean * mean;
    float scale = gamma2[c] * rsqrtf(var + 1e-5f);
    g_sb[c] = make_float2(scale, beta2[c] - mean * scale);
}

// ---------------- 6) normalize + ReLU + residual ----------------
__global__ void out_kernel(const float* __restrict__ x, float* __restrict__ out) {
    size_t i = ((size_t)blockIdx.x * 256 + threadIdx.x) << 2;
    int c = (int)((i >> 12) & 127);
    float2 sb = g_sb[c];
    float4 m  = *(const float4*)&g_med[i];
    float4 xv = *(const float4*)&x[i];
    float4 o;
    o.x = fmaxf(fmaf(m.x, sb.x, sb.y), 0.f) + xv.x;
    o.y = fmaxf(fmaf(m.y, sb.x, sb.y), 0.f) + xv.y;
    o.z = fmaxf(fmaf(m.z, sb.x, sb.y), 0.f) + xv.z;
    o.w = fmaxf(fmaf(m.w, sb.x, sb.y), 0.f) + xv.w;
    *(float4*)&out[i] = o;
}

// ---------------- launch ----------------
extern "C" void kernel_launch(void* const* d_in, const int* in_sizes, int n_in,
                              void* d_out, int out_size) {
    (void)in_sizes; (void)n_in; (void)out_size;
    const float* x      = (const float*)d_in[0];
    // d_in[1] = w1, d_in[3] = gamma1, d_in[4] = beta1: unused (reference discards out1)
    const float* w2     = (const float*)d_in[2];
    const float* gamma2 = (const float*)d_in[5];
    const float* beta2  = (const float*)d_in[6];
    const float* hs     = (const float*)d_in[7];
    const float* ss     = (const float*)d_in[8];
    float* out = (float*)d_out;

    const int DSMEM = 2 * ST_SZ;   // 129024 B, double-buffered stages
    cudaFuncSetAttribute(conv_mma_kernel, cudaFuncAttributeMaxDynamicSharedMemorySize, DSMEM);

    idx_kernel<<<2, 256>>>(hs);
    wsk_kernel<<<(CO_ * KTOT + 255) / 256, 256>>>(w2, ss);
    zero_kernel<<<(B_ * 260 * 16 + 255) / 256, 256>>>();
    xT_kernel<<<dim3(H_, B_), 256>>>(x);
    conv_mma_kernel<<<dim3(H_ / 2, B_), 256, DSMEM>>>(ss);
    stats1_kernel<<<dim3(C_, 8), 256>>>();
    stats2_kernel<<<1, C_>>>(gamma2, beta2);
    out_kernel<<<(B_ * C_ * HW_) / 1024, 256>>>(x, out);
}

// round 12
// speedup vs baseline: 1.7495x; 1.7495x over previous
#include <cuda_runtime.h>
#include <cuda_fp16.h>
#include <cstdint>

#define B_   32
#define C_   128
#define CO_  96
#define H_   64
#define W_   64
#define HW_  4096
#define HP_  66
#define WP_  66
#define KTOT 1152   // 9 taps * 128 ci

// ---------------- device scratch (no allocations allowed) ----------------
__device__ __align__(16) __half g_xp[(size_t)B_ * HP_ * WP_ * C_]; // padded NHWC fp16
__device__ __align__(16) __half g_w[CO_ * KTOT];                   // A: [co][tap*128+ci]
__device__ int    g_idx[3 * C_];
__device__ float  g_med[(size_t)B_ * C_ * HW_];
__device__ float2 g_part[C_ * 8];
__device__ float2 g_sb[C_];

// ---------------- PTX helpers (sm_80-era: safe for compute_103) ----------------
__device__ __forceinline__ uint32_t smem_u32(const void* p) {
    uint32_t a;
    asm("{ .reg .u64 t; cvta.to.shared.u64 t, %1; cvt.u32.u64 %0, t; }" : "=r"(a) : "l"(p));
    return a;
}
__device__ __forceinline__ void ldsm4(uint32_t* r, uint32_t addr) {
    asm volatile("ldmatrix.sync.aligned.m8n8.x4.shared.b16 {%0,%1,%2,%3}, [%4];"
        : "=r"(r[0]), "=r"(r[1]), "=r"(r[2]), "=r"(r[3]) : "r"(addr));
}
__device__ __forceinline__ void mma16816(float* d, const uint32_t* a, const uint32_t* b) {
    asm volatile("mma.sync.aligned.m16n8k16.row.col.f32.f16.f16.f32 "
        "{%0,%1,%2,%3}, {%4,%5,%6,%7}, {%8,%9}, {%0,%1,%2,%3};"
        : "+f"(d[0]), "+f"(d[1]), "+f"(d[2]), "+f"(d[3])
        : "r"(a[0]), "r"(a[1]), "r"(a[2]), "r"(a[3]), "r"(b[0]), "r"(b[1]));
}

// ---------------- 1) one-hot indices from hs ----------------
__global__ void idx_kernel(const float* __restrict__ hs) {
    int t = blockIdx.x * blockDim.x + threadIdx.x;
    if (t >= 3 * C_) return;
    int j = t >> 7, c = t & 127;
    int d = 0;
    for (int dd = 0; dd < 32; ++dd)
        if (hs[(j * 32 + dd) * C_ + c] > 0.5f) d = dd;
    g_idx[t] = d;
}

// ---------------- 2) sketched weights -> fp16, [co][tap*128+ci] ----------------
__global__ void wsk_kernel(const float* __restrict__ w2, const float* __restrict__ ss) {
    int e = blockIdx.x * 256 + threadIdx.x;
    if (e >= CO_ * KTOT) return;
    int ci = e & 127, tap = (e >> 7) % 9, co = e / KTOT;
    int j = co >> 5, d = co & 31;
    float sum = 0.f;
    for (int c = 0; c < C_; ++c) {
        int   ic = g_idx[j * C_ + c];
        float wv = w2[(c * C_ + ci) * 9 + tap];
        sum += (ic == d) ? ss[j * C_ + c] * wv : 0.f;
    }
    g_w[e] = __float2half_rn(sum);
}

// ---------------- 3a) zero padded borders of g_xp ----------------
__global__ void zero_kernel() {
    int t = blockIdx.x * 256 + threadIdx.x;          // B_ * 260 * 16
    if (t >= B_ * 260 * 16) return;
    int v  = t & 15;
    int pb = (t >> 4) % 260;
    int b  = t / (260 * 16);
    int h, w;
    if (pb < 66)       { h = 0;  w = pb; }
    else if (pb < 132) { h = 65; w = pb - 66; }
    else { int q = pb - 132; h = 1 + (q >> 1); w = (q & 1) * 65; }
    size_t off = (((size_t)b * HP_ + h) * WP_ + w) * C_ + v * 8;
    *(uint4*)(g_xp + off) = make_uint4(0, 0, 0, 0);
}

// ---------------- 3b) NCHW fp32 -> padded NHWC fp16 ----------------
__global__ __launch_bounds__(256) void xT_kernel(const float* __restrict__ x) {
    __shared__ float sm[128 * 65];
    const int t = threadIdx.x, h = blockIdx.x, b = blockIdx.y;
    const float* xp = x + (size_t)b * C_ * HW_ + h * W_;
#pragma unroll
    for (int k = 0; k < 32; ++k) {
        int idx = (k << 8) + t;
        int c = idx >> 6, w = idx & 63;
        sm[c * 65 + w] = xp[(size_t)c * HW_ + w];
    }
    __syncthreads();
    size_t dbase = (((size_t)b * HP_ + h + 1) * WP_ + 1) * C_;
#pragma unroll
    for (int k = 0; k < 16; ++k) {
        int idx = (k << 8) + t;
        int w = idx >> 6, c2 = idx & 63;
        float f0 = sm[(2 * c2) * 65 + w];
        float f1 = sm[(2 * c2 + 1) * 65 + w];
        __half2 hh = __floats2half2_rn(f0, f1);
        size_t o = dbase + (size_t)w * C_ + 2 * c2;
        *(unsigned*)(g_xp + o) = *(unsigned*)&hh;
    }
}

// ---------------- 4) mma.sync conv: M=96 co, N=128 pixels, K=18x64, fp16 1-term ----------------
// SMEM: sA[96][72] fp16 (13824 B) + sB[128][72] fp16 (18432 B) = 32256 B staging;
// epilogue reuses dsm as yt[96][132] f32 (50688 B) -> DSMEM = 50688.
__global__ __launch_bounds__(256, 2)
void conv_mma_kernel(const float* __restrict__ ss) {
    extern __shared__ __half dsm[];
    __half* sA = dsm;                 // 96*72
    __half* sB = sA + 96 * 72;        // 128*72

    const int tid = threadIdx.x, warp = tid >> 5, lane = tid & 31;
    const int b = blockIdx.y, h0 = blockIdx.x << 1;   // 2 output rows per CTA
    const int m0 = (warp >> 2) * 48;                  // 2 warps in M: 48 rows each
    const int n0 = (warp & 3) * 32;                   // 4 warps in N: 32 pixels each

    const uint32_t aA = smem_u32(sA), aB = smem_u32(sB);

    // ldmatrix per-lane offsets
    uint32_t a_off[3];
#pragma unroll
    for (int ti = 0; ti < 3; ++ti)
        a_off[ti] = (uint32_t)((m0 + ti * 16 + (lane & 15)) * 144 + (lane >> 4) * 16);
    uint32_t b_off[2];
    {
        int o = lane >> 3;
#pragma unroll
        for (int u = 0; u < 2; ++u) {
            int pix = n0 + u * 16 + (o >> 1) * 8 + (lane & 7);
            b_off[u] = (uint32_t)(pix * 144 + (o & 1) * 16);
        }
    }

    float acc[3][4][4];
#pragma unroll
    for (int ti = 0; ti < 3; ++ti)
#pragma unroll
        for (int tj = 0; tj < 4; ++tj)
#pragma unroll
            for (int v = 0; v < 4; ++v) acc[ti][tj][v] = 0.f;

#pragma unroll 1
    for (int chunk = 0; chunk < 18; ++chunk) {
        const int tap = chunk >> 1, half = chunk & 1;
        const int kh = tap / 3, kw = tap - kh * 3;
        const __half* wsrc = g_w + tap * 128 + half * 64;
        const __half* xsrc = g_xp
            + (((size_t)b * HP_ + h0 + kh) * WP_ + kw) * C_ + half * 64;

        __syncthreads();
        // stage A: 96 rows x 64 ci (3 uint4 per thread)
#pragma unroll
        for (int k = 0; k < 3; ++k) {
            int g = tid + (k << 8);
            int row = g >> 3, sub = g & 7;
            *(uint4*)(sA + row * 72 + sub * 8) = *(const uint4*)(wsrc + (size_t)row * KTOT + sub * 8);
        }
        // stage B: 128 pixel rows x 64 ci (4 uint4 per thread)
#pragma unroll
        for (int k = 0; k < 4; ++k) {
            int g = tid + (k << 8);
            int n = g >> 3, sub = g & 7;
            int r = n >> 6, wn = n & 63;
            size_t so = ((size_t)r * WP_ + wn) * C_ + sub * 8;
            *(uint4*)(sB + n * 72 + sub * 8) = *(const uint4*)(xsrc + so);
        }
        __syncthreads();

#pragma unroll
        for (int s = 0; s < 4; ++s) {
            uint32_t a[3][4], bb[8];
#pragma unroll
            for (int ti = 0; ti < 3; ++ti)
                ldsm4(a[ti], aA + a_off[ti] + s * 32);
#pragma unroll
            for (int u = 0; u < 2; ++u)
                ldsm4(&bb[u * 4], aB + b_off[u] + s * 32);
#pragma unroll
            for (int ti = 0; ti < 3; ++ti)
#pragma unroll
                for (int tj = 0; tj < 4; ++tj)
                    mma16816(acc[ti][tj], a[ti], &bb[tj * 2]);
        }
    }

    // ---- accumulators -> SMEM yt[96][132] (reuse staging smem) ----
    __syncthreads();
    float* yt = (float*)dsm;
#pragma unroll
    for (int ti = 0; ti < 3; ++ti)
#pragma unroll
        for (int tj = 0; tj < 4; ++tj) {
            int row = m0 + ti * 16 + (lane >> 2);
            int col = n0 + tj * 8 + (lane & 3) * 2;
            *(float2*)&yt[row * 132 + col]       = make_float2(acc[ti][tj][0], acc[ti][tj][1]);
            *(float2*)&yt[(row + 8) * 132 + col] = make_float2(acc[ti][tj][2], acc[ti][tj][3]);
        }
    __syncthreads();

    // ---- unsketch (gather + sign) + median-of-3, coalesced g_med store ----
    const int sp = tid & 127, cg = tid >> 7;
    const int hh = h0 + (sp >> 6), wn = sp & 63;
    float* mbase = g_med + ((size_t)b * C_) * HW_ + hh * W_ + wn;
#pragma unroll 1
    for (int cc = 0; cc < 64; ++cc) {
        int c = (cg << 6) + cc;
        int i0 = g_idx[c], i1 = g_idx[C_ + c], i2 = g_idx[2 * C_ + c];
        float s0 = ss[c], s1 = ss[C_ + c], s2 = ss[2 * C_ + c];
        float v0 = s0 * yt[i0 * 132 + sp];
        float v1 = s1 * yt[(32 + i1) * 132 + sp];
        float v2 = s2 * yt[(64 + i2) * 132 + sp];
        float mx = fmaxf(v0, v1), mn = fminf(v0, v1);
        mbase[(size_t)c * HW_] = fmaxf(mn, fminf(mx, v2));
    }
}

// ---------------- 5) BN stats, two-stage ----------------
__global__ void stats1_kernel() {
    const int c = blockIdx.x, q = blockIdx.y, tid = threadIdx.x;
    float s = 0.f, qq = 0.f;
    for (int bb = q * 4; bb < q * 4 + 4; ++bb) {
        const float4* p = (const float4*)(g_med + ((size_t)bb * C_ + c) * HW_);
        for (int i = tid; i < HW_ / 4; i += 256) {
            float4 v = p[i];
            s += v.x + v.y + v.z + v.w;
            qq = fmaf(v.x, v.x, fmaf(v.y, v.y, fmaf(v.z, v.z, fmaf(v.w, v.w, qq))));
        }
    }
    __shared__ float rs[8], rq[8];
#pragma unroll
    for (int o = 16; o; o >>= 1) {
        s  += __shfl_down_sync(0xffffffffu, s,  o);
        qq += __shfl_down_sync(0xffffffffu, qq, o);
    }
    if ((tid & 31) == 0) { rs[tid >> 5] = s; rq[tid >> 5] = qq; }
    __syncthreads();
    if (tid == 0) {
        float S = 0.f, Q = 0.f;
        for (int i = 0; i < 8; ++i) { S += rs[i]; Q += rq[i]; }
        g_part[c * 8 + q] = make_float2(S, Q);
    }
}
__global__ void stats2_kernel(const float* __restrict__ gamma2,
                              const float* __restrict__ beta2) {
    int c = threadIdx.x;
    float S = 0.f, Q = 0.f;
    for (int q = 0; q < 8; ++q) { float2 p = g_part[c * 8 + q]; S += p.x; Q += p.y; }
    const float invn = 1.f / (float)(B_ * HW_);
    float mean  = S * invn;
    float var   = Q * invn - mean * mean;
    float scale = gamma2[c] * rsqrtf(var + 1e-5f);
    g_sb[c] = make_float2(scale, beta2[c] - mean * scale);
}

// ---------------- 6) normalize + ReLU + residual ----------------
__global__ void out_kernel(const float* __restrict__ x, float* __restrict__ out) {
    size_t i = ((size_t)blockIdx.x * 256 + threadIdx.x) << 2;
    int c = (int)((i >> 12) & 127);
    float2 sb = g_sb[c];
    float4 m  = *(const float4*)&g_med[i];
    float4 xv = *(const float4*)&x[i];
    float4 o;
    o.x = fmaxf(fmaf(m.x, sb.x, sb.y), 0.f) + xv.x;
    o.y = fmaxf(fmaf(m.y, sb.x, sb.y), 0.f) + xv.y;
    o.z = fmaxf(fmaf(m.z, sb.x, sb.y), 0.f) + xv.z;
    o.w = fmaxf(fmaf(m.w, sb.x, sb.y), 0.f) + xv.w;
    *(float4*)&out[i] = o;
}

// ---------------- launch ----------------
extern "C" void kernel_launch(void* const* d_in, const int* in_sizes, int n_in,
                              void* d_out, int out_size) {
    (void)in_sizes; (void)n_in; (void)out_size;
    const float* x      = (const float*)d_in[0];
    // d_in[1] = w1, d_in[3] = gamma1, d_in[4] = beta1: unused (reference discards out1)
    const float* w2     = (const float*)d_in[2];
    const float* gamma2 = (const float*)d_in[5];
    const float* beta2  = (const float*)d_in[6];
    const float* hs     = (const float*)d_in[7];
    const float* ss     = (const float*)d_in[8];
    float* out = (float*)d_out;

    const int DSMEM = 96 * 132 * 4;   // 50688 B (epilogue yt dominates staging 32256 B)
    cudaFuncSetAttribute(conv_mma_kernel, cudaFuncAttributeMaxDynamicSharedMemorySize, DSMEM);

    idx_kernel<<<2, 256>>>(hs);
    wsk_kernel<<<(CO_ * KTOT + 255) / 256, 256>>>(w2, ss);
    zero_kernel<<<(B_ * 260 * 16 + 255) / 256, 256>>>();
    xT_kernel<<<dim3(H_, B_), 256>>>(x);
    conv_mma_kernel<<<dim3(H_ / 2, B_), 256, DSMEM>>>(ss);
    stats1_kernel<<<dim3(C_, 8), 256>>>();
    stats2_kernel<<<1, C_>>>(gamma2, beta2);
    out_kernel<<<(B_ * C_ * HW_) / 1024, 256>>>(x, out);
}

// round 13
// speedup vs baseline: 2.0771x; 1.1873x over previous
#include <cuda_runtime.h>
#include <cuda_fp16.h>
#include <cstdint>

#define B_   32
#define C_   128
#define CO_  96
#define H_   64
#define W_   64
#define HW_  4096
#define HP_  66
#define WP_  66
#define KTOT 1152   // 9 taps * 128 ci

// ---------------- device scratch (no allocations allowed) ----------------
__device__ __align__(16) __half g_xp[(size_t)B_ * HP_ * WP_ * C_]; // padded NHWC fp16
__device__ __align__(16) __half g_w[CO_ * KTOT];                   // A: [co][tap*128+ci]
__device__ int    g_idx[3 * C_];
__device__ __align__(16) __half g_medh[(size_t)B_ * C_ * HW_];     // median result, fp16 NCHW
__device__ float2 g_part[C_ * 8];
__device__ float2 g_sb[C_];

// ---------------- PTX helpers (sm_80-era: safe for compute_103) ----------------
__device__ __forceinline__ uint32_t smem_u32(const void* p) {
    uint32_t a;
    asm("{ .reg .u64 t; cvta.to.shared.u64 t, %1; cvt.u32.u64 %0, t; }" : "=r"(a) : "l"(p));
    return a;
}
__device__ __forceinline__ void ldsm4(uint32_t* r, uint32_t addr) {
    asm volatile("ldmatrix.sync.aligned.m8n8.x4.shared.b16 {%0,%1,%2,%3}, [%4];"
        : "=r"(r[0]), "=r"(r[1]), "=r"(r[2]), "=r"(r[3]) : "r"(addr));
}
__device__ __forceinline__ void mma16816(float* d, const uint32_t* a, const uint32_t* b) {
    asm volatile("mma.sync.aligned.m16n8k16.row.col.f32.f16.f16.f32 "
        "{%0,%1,%2,%3}, {%4,%5,%6,%7}, {%8,%9}, {%0,%1,%2,%3};"
        : "+f"(d[0]), "+f"(d[1]), "+f"(d[2]), "+f"(d[3])
        : "r"(a[0]), "r"(a[1]), "r"(a[2]), "r"(a[3]), "r"(b[0]), "r"(b[1]));
}

// SMEM layout (halves): sB halo [132][72] then sA [3][96][72]
#define SB_HALVES (132 * 72)   // 9504 halves = 19008 B
#define TILE_A    (96 * 72)    // 6912 halves = 13824 B
#define DSM_HALVES (SB_HALVES + 3 * TILE_A)   // 30240 halves = 60480 B

// ---------------- 1) one-hot indices from hs ----------------
__global__ void idx_kernel(const float* __restrict__ hs) {
    int t = blockIdx.x * blockDim.x + threadIdx.x;
    if (t >= 3 * C_) return;
    int j = t >> 7, c = t & 127;
    int d = 0;
    for (int dd = 0; dd < 32; ++dd)
        if (hs[(j * 32 + dd) * C_ + c] > 0.5f) d = dd;
    g_idx[t] = d;
}

// ---------------- 2) sketched weights -> fp16, [co][tap*128+ci] ----------------
__global__ void wsk_kernel(const float* __restrict__ w2, const float* __restrict__ ss) {
    int e = blockIdx.x * 256 + threadIdx.x;
    if (e >= CO_ * KTOT) return;
    int ci = e & 127, tap = (e >> 7) % 9, co = e / KTOT;
    int j = co >> 5, d = co & 31;
    float sum = 0.f;
    for (int c = 0; c < C_; ++c) {
        int   ic = g_idx[j * C_ + c];
        float wv = w2[(c * C_ + ci) * 9 + tap];
        sum += (ic == d) ? ss[j * C_ + c] * wv : 0.f;
    }
    g_w[e] = __float2half_rn(sum);
}

// ---------------- 3a) zero padded borders of g_xp ----------------
__global__ void zero_kernel() {
    int t = blockIdx.x * 256 + threadIdx.x;          // B_ * 260 * 16
    if (t >= B_ * 260 * 16) return;
    int v  = t & 15;
    int pb = (t >> 4) % 260;
    int b  = t / (260 * 16);
    int h, w;
    if (pb < 66)       { h = 0;  w = pb; }
    else if (pb < 132) { h = 65; w = pb - 66; }
    else { int q = pb - 132; h = 1 + (q >> 1); w = (q & 1) * 65; }
    size_t off = (((size_t)b * HP_ + h) * WP_ + w) * C_ + v * 8;
    *(uint4*)(g_xp + off) = make_uint4(0, 0, 0, 0);
}

// ---------------- 3b) NCHW fp32 -> padded NHWC fp16 ----------------
__global__ __launch_bounds__(256) void xT_kernel(const float* __restrict__ x) {
    __shared__ float sm[128 * 65];
    const int t = threadIdx.x, h = blockIdx.x, b = blockIdx.y;
    const float* xp = x + (size_t)b * C_ * HW_ + h * W_;
#pragma unroll
    for (int k = 0; k < 32; ++k) {
        int idx = (k << 8) + t;
        int c = idx >> 6, w = idx & 63;
        sm[c * 65 + w] = xp[(size_t)c * HW_ + w];
    }
    __syncthreads();
    size_t dbase = (((size_t)b * HP_ + h + 1) * WP_ + 1) * C_;
#pragma unroll
    for (int k = 0; k < 16; ++k) {
        int idx = (k << 8) + t;
        int w = idx >> 6, c2 = idx & 63;
        float f0 = sm[(2 * c2) * 65 + w];
        float f1 = sm[(2 * c2 + 1) * 65 + w];
        __half2 hh = __floats2half2_rn(f0, f1);
        size_t o = dbase + (size_t)w * C_ + 2 * c2;
        *(unsigned*)(g_xp + o) = *(unsigned*)&hh;
    }
}

// ---------------- 4) mma.sync conv with B-halo reuse across kw ----------------
__global__ __launch_bounds__(256, 2)
void conv_mma_kernel(const float* __restrict__ ss) {
    extern __shared__ __half dsm[];
    __half* sB = dsm;                  // halo: 132 pixel-rows x 72 (64 used)
    __half* sA = dsm + SB_HALVES;      // 3 kw tiles x 96 rows x 72

    const int tid = threadIdx.x, warp = tid >> 5, lane = tid & 31;
    const int b = blockIdx.y, h0 = blockIdx.x << 1;   // 2 output rows per CTA
    const int m0 = (warp >> 2) * 48;                  // 2 warps in M: 48 rows each
    const int n0 = (warp & 3) * 32;                   // 4 warps in N: 32 pixels each

    const uint32_t aB = smem_u32(sB), aA = smem_u32(sA);

    // ldmatrix per-lane offsets
    uint32_t a_off[3];
#pragma unroll
    for (int ti = 0; ti < 3; ++ti)
        a_off[ti] = (uint32_t)((m0 + ti * 16 + (lane & 15)) * 144 + (lane >> 4) * 16);
    uint32_t b_off[2];
    {
        int o = lane >> 3;
#pragma unroll
        for (int u = 0; u < 2; ++u) {
            int pix  = n0 + u * 16 + (o >> 1) * 8 + (lane & 7);
            int hrow = (pix >> 6) * 66 + (pix & 63);       // halo row (2 x 66 layout)
            b_off[u] = (uint32_t)(hrow * 144 + (o & 1) * 16);
        }
    }

    float acc[3][4][4];
#pragma unroll
    for (int ti = 0; ti < 3; ++ti)
#pragma unroll
        for (int tj = 0; tj < 4; ++tj)
#pragma unroll
            for (int v = 0; v < 4; ++v) acc[ti][tj][v] = 0.f;

#pragma unroll 1
    for (int it = 0; it < 6; ++it) {
        const int kh = it >> 1, half = it & 1;
        __syncthreads();
        // stage B halo: 132 rows (2 x 66 cols) x 64 ci = 1056 uint4
        const __half* xb = g_xp + (((size_t)b * HP_ + h0 + kh) * WP_) * C_ + half * 64;
#pragma unroll
        for (int k = 0; k < 5; ++k) {
            int g = tid + (k << 8);
            if (g < 1056) {
                int row = g >> 3, sub = g & 7;
                int r = (row >= 66) ? 1 : 0;
                int wn = row - r * 66;
                *(uint4*)(sB + row * 72 + sub * 8) =
                    *(const uint4*)(xb + ((size_t)r * WP_ + wn) * C_ + sub * 8);
            }
        }
        // stage A: 3 kw tiles, 96 rows x 64 ci each = 2304 uint4 (9 per thread)
        const __half* wb = g_w + (kh * 3) * 128 + half * 64;
#pragma unroll
        for (int k = 0; k < 9; ++k) {
            int g = tid + (k << 8);
            int tl = g / 768, rem = g - tl * 768;
            int row = rem >> 3, sub = rem & 7;
            *(uint4*)(sA + tl * TILE_A + row * 72 + sub * 8) =
                *(const uint4*)(wb + (size_t)row * KTOT + tl * 128 + sub * 8);
        }
        __syncthreads();

#pragma unroll
        for (int kw = 0; kw < 3; ++kw) {
#pragma unroll
            for (int s = 0; s < 4; ++s) {
                uint32_t a[3][4], bb2[8];
#pragma unroll
                for (int ti = 0; ti < 3; ++ti)
                    ldsm4(a[ti], aA + kw * 13824 + a_off[ti] + s * 32);
#pragma unroll
                for (int u = 0; u < 2; ++u)
                    ldsm4(&bb2[u * 4], aB + b_off[u] + kw * 144 + s * 32);
#pragma unroll
                for (int ti = 0; ti < 3; ++ti)
#pragma unroll
                    for (int tj = 0; tj < 4; ++tj)
                        mma16816(acc[ti][tj], a[ti], &bb2[tj * 2]);
            }
        }
    }

    // ---- accumulators -> SMEM yt[96][132] (reuse staging smem) ----
    __syncthreads();
    float* yt = (float*)dsm;
#pragma unroll
    for (int ti = 0; ti < 3; ++ti)
#pragma unroll
        for (int tj = 0; tj < 4; ++tj) {
            int row = m0 + ti * 16 + (lane >> 2);
            int col = n0 + tj * 8 + (lane & 3) * 2;
            *(float2*)&yt[row * 132 + col]       = make_float2(acc[ti][tj][0], acc[ti][tj][1]);
            *(float2*)&yt[(row + 8) * 132 + col] = make_float2(acc[ti][tj][2], acc[ti][tj][3]);
        }
    __syncthreads();

    // ---- unsketch (gather + sign) + median-of-3, fp16 coalesced store ----
    const int sp = tid & 127, cg = tid >> 7;
    const int hh = h0 + (sp >> 6), wn = sp & 63;
    __half* mbase = g_medh + ((size_t)b * C_) * HW_ + hh * W_ + wn;
#pragma unroll 1
    for (int cc = 0; cc < 64; ++cc) {
        int c = (cg << 6) + cc;
        int i0 = g_idx[c], i1 = g_idx[C_ + c], i2 = g_idx[2 * C_ + c];
        float s0 = ss[c], s1 = ss[C_ + c], s2 = ss[2 * C_ + c];
        float v0 = s0 * yt[i0 * 132 + sp];
        float v1 = s1 * yt[(32 + i1) * 132 + sp];
        float v2 = s2 * yt[(64 + i2) * 132 + sp];
        float mx = fmaxf(v0, v1), mn = fminf(v0, v1);
        mbase[(size_t)c * HW_] = __float2half_rn(fmaxf(mn, fminf(mx, v2)));
    }
}

// ---------------- 5) BN stats (fp16 med), two-stage ----------------
__global__ void stats1_kernel() {
    const int c = blockIdx.x, q = blockIdx.y, tid = threadIdx.x;
    float s = 0.f, qq = 0.f;
    for (int bb = q * 4; bb < q * 4 + 4; ++bb) {
        const uint4* p = (const uint4*)(g_medh + ((size_t)bb * C_ + c) * HW_);
        for (int i = tid; i < HW_ / 8; i += 256) {
            uint4 v = p[i];
            const uint32_t wrd[4] = {v.x, v.y, v.z, v.w};
#pragma unroll
            for (int u = 0; u < 4; ++u) {
                float2 f = __half22float2(*(const __half2*)&wrd[u]);
                s += f.x + f.y;
                qq = fmaf(f.x, f.x, fmaf(f.y, f.y, qq));
            }
        }
    }
    __shared__ float rs[8], rq[8];
#pragma unroll
    for (int o = 16; o; o >>= 1) {
        s  += __shfl_down_sync(0xffffffffu, s,  o);
        qq += __shfl_down_sync(0xffffffffu, qq, o);
    }
    if ((tid & 31) == 0) { rs[tid >> 5] = s; rq[tid >> 5] = qq; }
    __syncthreads();
    if (tid == 0) {
        float S = 0.f, Q = 0.f;
        for (int i = 0; i < 8; ++i) { S += rs[i]; Q += rq[i]; }
        g_part[c * 8 + q] = make_float2(S, Q);
    }
}
__global__ void stats2_kernel(const float* __restrict__ gamma2,
                              const float* __restrict__ beta2) {
    int c = threadIdx.x;
    float S = 0.f, Q = 0.f;
    for (int q = 0; q < 8; ++q) { float2 p = g_part[c * 8 + q]; S += p.x; Q += p.y; }
    const float invn = 1.f / (float)(B_ * HW_);
    float mean  = S * invn;
    float var   = Q * invn - mean * mean;
    float scale = gamma2[c] * rsqrtf(var + 1e-5f);
    g_sb[c] = make_float2(scale, beta2[c] - mean * scale);
}

// ---------------- 6) normalize + ReLU + residual ----------------
__global__ void out_kernel(const float* __restrict__ x, float* __restrict__ out) {
    size_t i = ((size_t)blockIdx.x * 256 + threadIdx.x) << 2;
    int c = (int)((i >> 12) & 127);
    float2 sb = g_sb[c];
    uint2 mh = *(const uint2*)&g_medh[i];
    float2 f01 = __half22float2(*(const __half2*)&mh.x);
    float2 f23 = __half22float2(*(const __half2*)&mh.y);
    float4 xv = *(const float4*)&x[i];
    float4 o;
    o.x = fmaxf(fmaf(f01.x, sb.x, sb.y), 0.f) + xv.x;
    o.y = fmaxf(fmaf(f01.y, sb.x, sb.y), 0.f) + xv.y;
    o.z = fmaxf(fmaf(f23.x, sb.x, sb.y), 0.f) + xv.z;
    o.w = fmaxf(fmaf(f23.y, sb.x, sb.y), 0.f) + xv.w;
    *(float4*)&out[i] = o;
}

// ---------------- launch ----------------
extern "C" void kernel_launch(void* const* d_in, const int* in_sizes, int n_in,
                              void* d_out, int out_size) {
    (void)in_sizes; (void)n_in; (void)out_size;
    const float* x      = (const float*)d_in[0];
    // d_in[1] = w1, d_in[3] = gamma1, d_in[4] = beta1: unused (reference discards out1)
    const float* w2     = (const float*)d_in[2];
    const float* gamma2 = (const float*)d_in[5];
    const float* beta2  = (const float*)d_in[6];
    const float* hs     = (const float*)d_in[7];
    const float* ss     = (const float*)d_in[8];
    float* out = (float*)d_out;

    const int DSMEM = DSM_HALVES * 2;   // 60480 B (epilogue yt 50688 B fits)
    cudaFuncSetAttribute(conv_mma_kernel, cudaFuncAttributeMaxDynamicSharedMemorySize, DSMEM);

    idx_kernel<<<2, 256>>>(hs);
    wsk_kernel<<<(CO_ * KTOT + 255) / 256, 256>>>(w2, ss);
    zero_kernel<<<(B_ * 260 * 16 + 255) / 256, 256>>>();
    xT_kernel<<<dim3(H_, B_), 256>>>(x);
    conv_mma_kernel<<<dim3(H_ / 2, B_), 256, DSMEM>>>(ss);
    stats1_kernel<<<dim3(C_, 8), 256>>>();
    stats2_kernel<<<1, C_>>>(gamma2, beta2);
    out_kernel<<<(B_ * C_ * HW_) / 1024, 256>>>(x, out);
}